// round 5
// baseline (speedup 1.0000x reference)
#include <cuda_runtime.h>
#include <cuda_bf16.h>
#include <cstdint>

#define NB   2
#define NC   256
#define NPIX 4096
#define CI   128
#define EPSV 1e-5f

__device__ float g_E  [(size_t)NB * NPIX * NPIX];
__device__ float g_ET [(size_t)NB * NPIX * NPIX];
__device__ float g_VTQ[(size_t)NB * CI * NPIX];
__device__ float g_VTS[(size_t)NB * CI * NPIX];
__device__ float g_KT [(size_t)NB * NPIX * CI];
__device__ float g_QT [(size_t)NB * NPIX * CI];
__device__ float g_ST [(size_t)NB * CI * NPIX];
__device__ float g_TQ [(size_t)NB * CI * NPIX];
__device__ float g_rowsum[NB * NPIX];
__device__ float g_colsum[NB * NPIX];

// ---------------- helpers ----------------
__device__ __forceinline__ uint32_t smem_u32(const void* p) {
    uint32_t a;
    asm("{ .reg .u64 t; cvta.to.shared.u64 t, %1; cvt.u32.u64 %0, t; }" : "=r"(a) : "l"(p));
    return a;
}
__device__ __forceinline__ void cp16(uint32_t dst, const void* src) {
    asm volatile("cp.async.cg.shared.global [%0], [%1], 16;" :: "r"(dst), "l"(src));
}
#define CP_COMMIT() asm volatile("cp.async.commit_group;" ::: "memory")
#define CP_WAIT(n)  asm volatile("cp.async.wait_group %0;" :: "n"(n) : "memory")

__device__ __forceinline__ void mma_bf16(float* c, const uint32_t* a, uint32_t b0, uint32_t b1) {
    asm("mma.sync.aligned.m16n8k16.row.col.f32.bf16.bf16.f32 "
        "{%0,%1,%2,%3},{%4,%5,%6,%7},{%8,%9},{%0,%1,%2,%3};"
        : "+f"(c[0]), "+f"(c[1]), "+f"(c[2]), "+f"(c[3])
        : "r"(a[0]), "r"(a[1]), "r"(a[2]), "r"(a[3]), "r"(b0), "r"(b1));
}
// split two f32 into packed bf16 hi pair (ret) and lo pair (out param)
__device__ __forceinline__ uint32_t split2(float x, float y, uint32_t& lo) {
    __nv_bfloat16 hx = __float2bfloat16(x), hy = __float2bfloat16(y);
    uint32_t hi = (uint32_t)__bfloat16_as_ushort(hx) | ((uint32_t)__bfloat16_as_ushort(hy) << 16);
    __nv_bfloat16 lx = __float2bfloat16(x - __bfloat162float(hx));
    __nv_bfloat16 ly = __float2bfloat16(y - __bfloat162float(hy));
    lo = (uint32_t)__bfloat16_as_ushort(lx) | ((uint32_t)__bfloat16_as_ushort(ly) << 16);
    return hi;
}

// one k16 MMA macro-step: bf16x3 (hh + lh + hl), fragments from f32 smem
template<int STRIDE>
__device__ __forceinline__ void mma_step(const float* As, const float* Bs, int k0,
                                         int wr, int wc, int g, int tg, float c[2][8][4])
{
    uint32_t ah[2][4], al[2][4];
    #pragma unroll
    for (int mt = 0; mt < 2; mt++) {
        const float* a1 = As + (wr + mt * 16 + g) * STRIDE + k0 + tg * 2;
        const float* a2 = a1 + 8 * STRIDE;
        ah[mt][0] = split2(a1[0], a1[1], al[mt][0]);
        ah[mt][1] = split2(a2[0], a2[1], al[mt][1]);
        ah[mt][2] = split2(a1[8], a1[9], al[mt][2]);
        ah[mt][3] = split2(a2[8], a2[9], al[mt][3]);
    }
    #pragma unroll
    for (int nt = 0; nt < 8; nt++) {
        const float* bp = Bs + (wc + nt * 8 + g) * STRIDE + k0 + tg * 2;
        uint32_t bl0, bl1;
        uint32_t bh0 = split2(bp[0], bp[1], bl0);
        uint32_t bh1 = split2(bp[8], bp[9], bl1);
        #pragma unroll
        for (int mt = 0; mt < 2; mt++) {
            mma_bf16(c[mt][nt], ah[mt], bh0, bh1);
            mma_bf16(c[mt][nt], al[mt], bh0, bh1);
            mma_bf16(c[mt][nt], ah[mt], bl0, bl1);
        }
    }
}

// ---------------- zero sums ----------------
__global__ void zero_sums() {
    int i = blockIdx.x * 256 + threadIdx.x;
    if (i < NB * NPIX) { g_rowsum[i] = 0.f; g_colsum[i] = 0.f; }
}

// ============ gemmA: E = exp(KT . QT^T), bf16x3, fused sums ============
// smem: A [128][132] f32 @0 (67584B), B [128][132] @67584; total 135168. Tb aliases A.
#define GA_SMEM 135168
__global__ __launch_bounds__(256) void gemmA_mma()
{
    extern __shared__ char sm[];
    float* As = (float*)sm;
    float* Bs = (float*)(sm + 67584);
    const int t = threadIdx.x, lane = t & 31, wid = t >> 5;
    const int g = lane >> 2, tg = lane & 3;
    const int b = blockIdx.z, n0 = blockIdx.x * 128, m0 = blockIdx.y * 128;
    const int wr = (wid & 3) * 32, wc = (wid >> 2) * 64;
    const float* Ap = g_KT + (size_t)b * NPIX * CI + (size_t)n0 * CI;
    const float* Bp = g_QT + (size_t)b * NPIX * CI + (size_t)m0 * CI;
    uint32_t sb = smem_u32(sm);

    // bulk load both operands (128 rows x 128 floats each)
    #pragma unroll
    for (int p = 0; p < 16; p++) {
        int i = t + p * 256;              // 0..4095
        int row = i >> 5, seg = i & 31;   // seg: 16B units
        cp16(sb + row * 528 + seg * 16, Ap + (size_t)row * CI + seg * 4);
        cp16(sb + 67584 + row * 528 + seg * 16, Bp + (size_t)row * CI + seg * 4);
    }
    CP_COMMIT();
    CP_WAIT(0);
    __syncthreads();

    float c[2][8][4] = {};
    #pragma unroll
    for (int k0 = 0; k0 < 128; k0 += 16)
        mma_step<132>(As, Bs, k0, wr, wc, g, tg, c);
    __syncthreads();

    float* Tb = (float*)sm;    // [128][132], aliases A
    #pragma unroll
    for (int mt = 0; mt < 2; mt++)
        #pragma unroll
        for (int nt = 0; nt < 8; nt++)
            #pragma unroll
            for (int i = 0; i < 4; i++) {
                int row = wr + mt * 16 + g + (i >> 1) * 8;
                int col = wc + nt * 8 + tg * 2 + (i & 1);
                Tb[row * 132 + col] = __expf(c[mt][nt][i]);
            }
    __syncthreads();

    float* Eb  = g_E  + (size_t)b * NPIX * NPIX;
    float* ETb = g_ET + (size_t)b * NPIX * NPIX;
    for (int i = t; i < 4096; i += 256) {                 // E: float4 rows
        int r = i >> 5, c4 = (i & 31) * 4;
        *(float4*)(Eb + (size_t)(n0 + r) * NPIX + m0 + c4) = *(float4*)(Tb + r * 132 + c4);
    }
    for (int i = t; i < 4096; i += 256) {                 // ET: gather col, float4 store
        int cl = i >> 5, rq = (i & 31) * 4;
        float4 v;
        v.x = Tb[(rq + 0) * 132 + cl];
        v.y = Tb[(rq + 1) * 132 + cl];
        v.z = Tb[(rq + 2) * 132 + cl];
        v.w = Tb[(rq + 3) * 132 + cl];
        *(float4*)(ETb + (size_t)(m0 + cl) * NPIX + n0 + rq) = v;
    }
    if (t < 128) {
        float s = 0.f;
        #pragma unroll 8
        for (int j = 0; j < 128; j++) s += Tb[t * 132 + j];
        atomicAdd(g_rowsum + b * NPIX + n0 + t, s);
    } else {
        int cl = t - 128;
        float s = 0.f;
        #pragma unroll 8
        for (int j = 0; j < 128; j++) s += Tb[j * 132 + cl];
        atomicAdd(g_colsum + b * NPIX + m0 + cl, s);
    }
}

// ============ pv: out[c][r] = scale*(E . VT^T)/sum + T, cp.async pipelined ============
// smem: A stages [2][128][68] f32 @0 (2*34816), B stages @69632, RS @139264. Tb aliases A.
#define PV_SMEM 139776
__global__ __launch_bounds__(256) void pv_mma(const float* __restrict__ scale_p,
                                              float* __restrict__ outEq,
                                              float* __restrict__ outEs)
{
    extern __shared__ char sm[];
    const int t = threadIdx.x, lane = t & 31, wid = t >> 5;
    const int g = lane >> 2, tg = lane & 3;
    const int r0 = blockIdx.x * 128, b = blockIdx.y, mode = blockIdx.z;
    const int wr = (wid & 3) * 32, wc = (wid >> 2) * 64;
    const float* Ap = (mode ? g_ET : g_E) + (size_t)b * NPIX * NPIX + (size_t)r0 * NPIX;
    const float* Bp = (mode ? g_VTQ : g_VTS) + (size_t)b * CI * NPIX;
    const float* sums = (mode ? g_colsum : g_rowsum) + (size_t)b * NPIX + r0;
    const float* T = (mode ? g_TQ : g_ST) + (size_t)b * CI * NPIX;
    float* outp = (mode ? outEq : outEs) + (size_t)b * CI * NPIX;
    uint32_t sb = smem_u32(sm);
    float* RS = (float*)(sm + 139264);
    if (t < 128) RS[t] = scale_p[0] / sums[t];

    // preload chunk 0 into stage 0
    #pragma unroll
    for (int p = 0; p < 8; p++) {
        int i = t + p * 256;
        int row = i >> 4, seg = i & 15;
        cp16(sb + row * 272 + seg * 16, Ap + (size_t)row * NPIX + seg * 4);
        cp16(sb + 69632 + row * 272 + seg * 16, Bp + (size_t)row * NPIX + seg * 4);
    }
    CP_COMMIT();

    float c[2][8][4] = {};
    for (int kc = 0; kc < 64; kc++) {
        const int st = kc & 1;
        if (kc + 1 < 64) {
            const int st2 = (kc + 1) & 1;
            const float* An = Ap + (kc + 1) * 64;
            const float* Bn = Bp + (kc + 1) * 64;
            #pragma unroll
            for (int p = 0; p < 8; p++) {
                int i = t + p * 256;
                int row = i >> 4, seg = i & 15;
                cp16(sb + st2 * 34816 + row * 272 + seg * 16, An + (size_t)row * NPIX + seg * 4);
                cp16(sb + 69632 + st2 * 34816 + row * 272 + seg * 16, Bn + (size_t)row * NPIX + seg * 4);
            }
            CP_COMMIT();
            CP_WAIT(1);
        } else {
            CP_WAIT(0);
        }
        __syncthreads();
        const float* As = (const float*)(sm + st * 34816);
        const float* Bs = (const float*)(sm + 69632 + st * 34816);
        #pragma unroll
        for (int k0 = 0; k0 < 64; k0 += 16)
            mma_step<68>(As, Bs, k0, wr, wc, g, tg, c);
        __syncthreads();
    }

    float* Tb = (float*)sm;   // [128][132], aliases A stages
    #pragma unroll
    for (int mt = 0; mt < 2; mt++)
        #pragma unroll
        for (int nt = 0; nt < 8; nt++)
            #pragma unroll
            for (int i = 0; i < 4; i++) {
                int row = wr + mt * 16 + g + (i >> 1) * 8;
                int col = wc + nt * 8 + tg * 2 + (i & 1);
                Tb[row * 132 + col] = c[mt][nt][i] * RS[row];
            }
    __syncthreads();
    for (int i = t; i < 16384; i += 256) {
        int cl = i >> 7, r = i & 127;
        size_t gi = (size_t)cl * NPIX + r0 + r;
        outp[gi] = Tb[r * 132 + cl] + T[gi];
    }
}

// ---------------- fused conv1x1: 12 jobs ----------------
__global__ __launch_bounds__(256) void convs_kernel(
    const float* __restrict__ q, const float* __restrict__ s,
    const float* __restrict__ w_v,  const float* __restrict__ b_v,
    const float* __restrict__ w_k1, const float* __restrict__ b_k1,
    const float* __restrict__ w_q1, const float* __restrict__ b_q1,
    const float* __restrict__ w_k2, const float* __restrict__ b_k2,
    const float* __restrict__ w_q2, const float* __restrict__ b_q2,
    const float* __restrict__ w_ts, const float* __restrict__ b_ts,
    const float* __restrict__ gts,  const float* __restrict__ bets,
    const float* __restrict__ mts,  const float* __restrict__ vts,
    const float* __restrict__ w_tq, const float* __restrict__ b_tq,
    const float* __restrict__ gtq,  const float* __restrict__ betq,
    const float* __restrict__ mtq,  const float* __restrict__ vtq)
{
    const int j = blockIdx.z, b = blockIdx.y, n0 = blockIdx.x * 128;
    const float *X, *W, *Bi, *bg = nullptr, *bb = nullptr, *bm = nullptr, *bv = nullptr;
    float* dst; int ocb = 0, co = 0; bool chanmaj = true, hasbn = false;
    switch (j) {
        case 0:  X = q; W = w_v;  Bi = b_v;  dst = g_VTQ; ocb = 0;  co = 0;  break;
        case 1:  X = q; W = w_v;  Bi = b_v;  dst = g_VTQ; ocb = 64; co = 64; break;
        case 2:  X = s; W = w_v;  Bi = b_v;  dst = g_VTS; ocb = 0;  co = 0;  break;
        case 3:  X = s; W = w_v;  Bi = b_v;  dst = g_VTS; ocb = 64; co = 64; break;
        case 4:  X = q; W = w_k1; Bi = b_k1; dst = g_KT;  chanmaj = false; co = 0;  break;
        case 5:  X = s; W = w_k2; Bi = b_k2; dst = g_KT;  chanmaj = false; co = 64; break;
        case 6:  X = q; W = w_q1; Bi = b_q1; dst = g_QT;  chanmaj = false; co = 0;  break;
        case 7:  X = s; W = w_q2; Bi = b_q2; dst = g_QT;  chanmaj = false; co = 64; break;
        case 8:  X = s; W = w_ts; Bi = b_ts; dst = g_ST;  ocb = 0;  co = 0;  hasbn = true; bg = gts; bb = bets; bm = mts; bv = vts; break;
        case 9:  X = s; W = w_ts; Bi = b_ts; dst = g_ST;  ocb = 64; co = 64; hasbn = true; bg = gts; bb = bets; bm = mts; bv = vts; break;
        case 10: X = q; W = w_tq; Bi = b_tq; dst = g_TQ;  ocb = 0;  co = 0;  hasbn = true; bg = gtq; bb = betq; bm = mtq; bv = vtq; break;
        default: X = q; W = w_tq; Bi = b_tq; dst = g_TQ;  ocb = 64; co = 64; hasbn = true; bg = gtq; bb = betq; bm = mtq; bv = vtq; break;
    }
    const float* Xb = X + (size_t)b * NC * NPIX;
    __shared__ float Ws[16][64];
    __shared__ float Xs[16][128];
    float acc[4][8] = {};
    const int t = threadIdx.x, rg = t >> 4, cg = t & 15;

    for (int k0 = 0; k0 < NC; k0 += 16) {
        for (int i = t; i < 1024; i += 256) {
            int oc = i >> 4, kk = i & 15;
            Ws[kk][oc] = W[(ocb + oc) * NC + k0 + kk];
        }
        for (int i = t; i < 2048; i += 256) {
            int kk = i >> 7, px = i & 127;
            Xs[kk][px] = Xb[(size_t)(k0 + kk) * NPIX + n0 + px];
        }
        __syncthreads();
        #pragma unroll
        for (int kk = 0; kk < 16; kk++) {
            float a[4], xv[8];
            #pragma unroll
            for (int i = 0; i < 4; i++) a[i] = Ws[kk][rg * 4 + i];
            #pragma unroll
            for (int jx = 0; jx < 8; jx++) xv[jx] = Xs[kk][cg * 8 + jx];
            #pragma unroll
            for (int i = 0; i < 4; i++)
                #pragma unroll
                for (int jx = 0; jx < 8; jx++) acc[i][jx] += a[i] * xv[jx];
        }
        __syncthreads();
    }
    #pragma unroll
    for (int i = 0; i < 4; i++) {
        int oc = rg * 4 + i, gi = ocb + oc;
        float sc = 1.f, off = Bi[gi];
        if (hasbn) {
            float inv = bg[gi] * rsqrtf(bv[gi] + EPSV);
            sc = inv; off = (Bi[gi] - bm[gi]) * inv + bb[gi];
        }
        #pragma unroll
        for (int jx = 0; jx < 8; jx++) {
            int px = cg * 8 + jx;
            float v = acc[i][jx] * sc + off;
            if (chanmaj) dst[((size_t)b * CI + co + oc) * NPIX + n0 + px] = v;
            else         dst[((size_t)b * NPIX + n0 + px) * CI + co + oc] = v;
        }
    }
}

// ---------------- 3x3 conv + BN + ReLU ----------------
__global__ __launch_bounds__(256) void conv3x3_kernel(
    const float* __restrict__ Wc,
    const float* __restrict__ bng, const float* __restrict__ bnb,
    const float* __restrict__ bnm, const float* __restrict__ bnv,
    const float* __restrict__ Eq, const float* __restrict__ Es,
    float* __restrict__ outp)
{
    const int b = blockIdx.y, y = blockIdx.x, zh = blockIdx.z;
    __shared__ float Xs[8][3][68];
    __shared__ float Wsm[8][9][64];
    const int t = threadIdx.x, pxg = t & 15, ocg = t >> 4;
    float acc[4][4] = {};

    for (int ic0 = 0; ic0 < 256; ic0 += 8) {
        const float* src = (ic0 < 128)
            ? Eq + ((size_t)b * CI + ic0) * NPIX
            : Es + ((size_t)b * CI + (ic0 - 128)) * NPIX;
        for (int i = t; i < 1584; i += 256) {
            int ic = i / 198, rem = i - ic * 198;
            int dy = rem / 66, xx = rem - dy * 66;
            int xg = xx - 1, yg = y + dy - 1;
            float v = 0.f;
            if (xg >= 0 && xg < 64 && yg >= 0 && yg < 64)
                v = src[(size_t)ic * NPIX + yg * 64 + xg];
            Xs[ic][dy][xx] = v;
        }
        for (int i = t; i < 4608; i += 256) {
            int oc = i / 72, rem = i - oc * 72;
            int icl = rem / 9, tap = rem - icl * 9;
            Wsm[icl][tap][oc] = Wc[(size_t)(zh * 64 + oc) * 2304 + (ic0 + icl) * 9 + tap];
        }
        __syncthreads();
        #pragma unroll
        for (int ic = 0; ic < 8; ic++)
            #pragma unroll
            for (int tap = 0; tap < 9; tap++) {
                const int dy = tap / 3, dx = tap - dy * 3;
                float w[4], xv[4];
                #pragma unroll
                for (int o = 0; o < 4; o++) w[o] = Wsm[ic][tap][ocg * 4 + o];
                #pragma unroll
                for (int p = 0; p < 4; p++) xv[p] = Xs[ic][dy][pxg * 4 + p + dx];
                #pragma unroll
                for (int o = 0; o < 4; o++)
                    #pragma unroll
                    for (int p = 0; p < 4; p++) acc[o][p] += w[o] * xv[p];
            }
        __syncthreads();
    }
    #pragma unroll
    for (int o = 0; o < 4; o++) {
        int oc = zh * 64 + ocg * 4 + o;
        float inv = bng[oc] * rsqrtf(bnv[oc] + EPSV);
        float off = bnb[oc] - bnm[oc] * inv;
        #pragma unroll
        for (int p = 0; p < 4; p++) {
            int px = pxg * 4 + p;
            outp[((size_t)b * CI + oc) * NPIX + y * 64 + px] = fmaxf(acc[o][p] * inv + off, 0.f);
        }
    }
}

// ---------------- launch ----------------
extern "C" void kernel_launch(void* const* d_in, const int* in_sizes, int n_in,
                              void* d_out, int out_size)
{
    (void)in_sizes; (void)n_in; (void)out_size;
    const float* q     = (const float*)d_in[0];
    const float* s     = (const float*)d_in[1];
    const float* scale = (const float*)d_in[2];
    const float* w_v   = (const float*)d_in[3];  const float* b_v  = (const float*)d_in[4];
    const float* w_k1  = (const float*)d_in[5];  const float* b_k1 = (const float*)d_in[6];
    const float* w_q1  = (const float*)d_in[7];  const float* b_q1 = (const float*)d_in[8];
    const float* w_k2  = (const float*)d_in[9];  const float* b_k2 = (const float*)d_in[10];
    const float* w_q2  = (const float*)d_in[11]; const float* b_q2 = (const float*)d_in[12];
    const float* w_ts  = (const float*)d_in[13]; const float* b_ts = (const float*)d_in[14];
    const float* gts   = (const float*)d_in[15]; const float* bets = (const float*)d_in[16];
    const float* mts   = (const float*)d_in[17]; const float* vts  = (const float*)d_in[18];
    const float* w_tq  = (const float*)d_in[19]; const float* b_tq = (const float*)d_in[20];
    const float* gtq   = (const float*)d_in[21]; const float* betq = (const float*)d_in[22];
    const float* mtq   = (const float*)d_in[23]; const float* vtq  = (const float*)d_in[24];
    const float* w_cat = (const float*)d_in[25];
    const float* gcat  = (const float*)d_in[26]; const float* becat= (const float*)d_in[27];
    const float* mcat  = (const float*)d_in[28]; const float* vcat = (const float*)d_in[29];

    float* out  = (float*)d_out;
    float* cpam = out;
    float* Eq   = out + (size_t)NB * CI * NPIX;
    float* Es   = out + 2 * (size_t)NB * CI * NPIX;

    cudaFuncSetAttribute(gemmA_mma, cudaFuncAttributeMaxDynamicSharedMemorySize, GA_SMEM);
    cudaFuncSetAttribute(pv_mma,   cudaFuncAttributeMaxDynamicSharedMemorySize, PV_SMEM);

    zero_sums<<<(NB * NPIX + 255) / 256, 256>>>();
    convs_kernel<<<dim3(32, NB, 12), 256>>>(q, s, w_v, b_v, w_k1, b_k1, w_q1, b_q1,
                                            w_k2, b_k2, w_q2, b_q2, w_ts, b_ts,
                                            gts, bets, mts, vts, w_tq, b_tq,
                                            gtq, betq, mtq, vtq);
    gemmA_mma<<<dim3(32, 32, NB), 256, GA_SMEM>>>();
    pv_mma<<<dim3(32, NB, 2), 256, PV_SMEM>>>(scale, Eq, Es);
    conv3x3_kernel<<<dim3(64, NB, 2), 256>>>(w_cat, gcat, becat, mcat, vcat, Eq, Es, cpam);
}

// round 6
// speedup vs baseline: 1.2004x; 1.2004x over previous
#include <cuda_runtime.h>
#include <cuda_bf16.h>
#include <cstdint>

#define NB   2
#define NC   256
#define NPIX 4096
#define CI   128
#define EPSV 1e-5f

typedef __nv_bfloat16 bf16;

// bf16 hi/lo planes for all GEMM operands
__device__ bf16 g_Ehi [(size_t)NB * NPIX * NPIX];
__device__ bf16 g_Elo [(size_t)NB * NPIX * NPIX];
__device__ bf16 g_EThi[(size_t)NB * NPIX * NPIX];
__device__ bf16 g_ETlo[(size_t)NB * NPIX * NPIX];
__device__ bf16 g_VQhi[(size_t)NB * CI * NPIX];
__device__ bf16 g_VQlo[(size_t)NB * CI * NPIX];
__device__ bf16 g_VShi[(size_t)NB * CI * NPIX];
__device__ bf16 g_VSlo[(size_t)NB * CI * NPIX];
__device__ bf16 g_KThi[(size_t)NB * NPIX * CI];
__device__ bf16 g_KTlo[(size_t)NB * NPIX * CI];
__device__ bf16 g_QThi[(size_t)NB * NPIX * CI];
__device__ bf16 g_QTlo[(size_t)NB * NPIX * CI];
__device__ float g_ST [(size_t)NB * CI * NPIX];
__device__ float g_TQ [(size_t)NB * CI * NPIX];
__device__ float g_rowsum[NB * NPIX];
__device__ float g_colsum[NB * NPIX];

// ---------------- helpers ----------------
__device__ __forceinline__ uint32_t smem_u32(const void* p) {
    uint32_t a;
    asm("{ .reg .u64 t; cvta.to.shared.u64 t, %1; cvt.u32.u64 %0, t; }" : "=r"(a) : "l"(p));
    return a;
}
__device__ __forceinline__ void cp16(uint32_t dst, const void* src) {
    asm volatile("cp.async.cg.shared.global [%0], [%1], 16;" :: "r"(dst), "l"(src));
}
#define CP_COMMIT() asm volatile("cp.async.commit_group;" ::: "memory")
#define CP_WAIT(n)  asm volatile("cp.async.wait_group %0;" :: "n"(n) : "memory")

__device__ __forceinline__ void mma_bf16(float* c, const uint32_t* a, uint32_t b0, uint32_t b1) {
    asm("mma.sync.aligned.m16n8k16.row.col.f32.bf16.bf16.f32 "
        "{%0,%1,%2,%3},{%4,%5,%6,%7},{%8,%9},{%0,%1,%2,%3};"
        : "+f"(c[0]), "+f"(c[1]), "+f"(c[2]), "+f"(c[3])
        : "r"(a[0]), "r"(a[1]), "r"(a[2]), "r"(a[3]), "r"(b0), "r"(b1));
}
__device__ __forceinline__ uint32_t split2(float x, float y, uint32_t& lo) {
    bf16 hx = __float2bfloat16(x), hy = __float2bfloat16(y);
    uint32_t hi = (uint32_t)__bfloat16_as_ushort(hx) | ((uint32_t)__bfloat16_as_ushort(hy) << 16);
    bf16 lx = __float2bfloat16(x - __bfloat162float(hx));
    bf16 ly = __float2bfloat16(y - __bfloat162float(hy));
    lo = (uint32_t)__bfloat16_as_ushort(lx) | ((uint32_t)__bfloat16_as_ushort(ly) << 16);
    return hi;
}

// one k16 MMA macro-step from bf16 hi/lo smem (uint32 stride ST), pure lds+mma
template<int ST>
__device__ __forceinline__ void mma_step(const uint32_t* Ahi, const uint32_t* Alo,
                                         const uint32_t* Bhi, const uint32_t* Blo,
                                         int kb, int wr, int wc, int g, int tg, float c[2][8][4])
{
    uint32_t ah[2][4], al[2][4];
    #pragma unroll
    for (int mt = 0; mt < 2; mt++) {
        int base = (wr + mt * 16 + g) * ST + kb + tg;
        ah[mt][0] = Ahi[base];          ah[mt][1] = Ahi[base + 8 * ST];
        ah[mt][2] = Ahi[base + 4];      ah[mt][3] = Ahi[base + 8 * ST + 4];
        al[mt][0] = Alo[base];          al[mt][1] = Alo[base + 8 * ST];
        al[mt][2] = Alo[base + 4];      al[mt][3] = Alo[base + 8 * ST + 4];
    }
    #pragma unroll
    for (int nt = 0; nt < 8; nt++) {
        int bb = (wc + nt * 8 + g) * ST + kb + tg;
        uint32_t bh0 = Bhi[bb], bh1 = Bhi[bb + 4];
        uint32_t bl0 = Blo[bb], bl1 = Blo[bb + 4];
        #pragma unroll
        for (int mt = 0; mt < 2; mt++) {
            mma_bf16(c[mt][nt], ah[mt], bh0, bh1);
            mma_bf16(c[mt][nt], al[mt], bh0, bh1);
            mma_bf16(c[mt][nt], ah[mt], bl0, bl1);
        }
    }
}

__global__ void zero_sums() {
    int i = blockIdx.x * 256 + threadIdx.x;
    if (i < NB * NPIX) { g_rowsum[i] = 0.f; g_colsum[i] = 0.f; }
}

// ============ gemmA: E = exp(KT . QT^T), pure lds+mma, fused sums ============
// smem arrays (uint32 stride 68 = 272B/row): Ahi@0 Alo@34816 Bhi@69632 Blo@104448
#define GA_SMEM 139264
__global__ __launch_bounds__(256) void gemmA_mma()
{
    extern __shared__ char sm[];
    const int t = threadIdx.x, lane = t & 31, wid = t >> 5;
    const int g = lane >> 2, tg = lane & 3;
    const int b = blockIdx.z, n0 = blockIdx.x * 128, m0 = blockIdx.y * 128;
    const int wr = (wid & 3) * 32, wc = (wid >> 2) * 64;
    const bf16* A_hi = g_KThi + (size_t)b * NPIX * CI + (size_t)n0 * CI;
    const bf16* A_lo = g_KTlo + (size_t)b * NPIX * CI + (size_t)n0 * CI;
    const bf16* B_hi = g_QThi + (size_t)b * NPIX * CI + (size_t)m0 * CI;
    const bf16* B_lo = g_QTlo + (size_t)b * NPIX * CI + (size_t)m0 * CI;
    uint32_t sb = smem_u32(sm);

    #pragma unroll
    for (int p = 0; p < 8; p++) {
        int i = t + p * 256;               // 0..2047
        int row = i >> 4, seg = i & 15;    // 16 x 16B = 256B = 128 bf16 per row
        size_t go = (size_t)row * CI + seg * 8;
        uint32_t so = row * 272 + seg * 16;
        cp16(sb + so,          A_hi + go);
        cp16(sb + 34816 + so,  A_lo + go);
        cp16(sb + 69632 + so,  B_hi + go);
        cp16(sb + 104448 + so, B_lo + go);
    }
    CP_COMMIT();
    CP_WAIT(0);
    __syncthreads();

    const uint32_t* Ahi = (const uint32_t*)sm;
    const uint32_t* Alo = (const uint32_t*)(sm + 34816);
    const uint32_t* Bhi = (const uint32_t*)(sm + 69632);
    const uint32_t* Blo = (const uint32_t*)(sm + 104448);
    float c[2][8][4] = {};
    #pragma unroll
    for (int kb = 0; kb < 64; kb += 8)
        mma_step<68>(Ahi, Alo, Bhi, Blo, kb, wr, wc, g, tg, c);
    __syncthreads();

    float* Tb = (float*)sm;    // [128][132] f32, aliases operands
    #pragma unroll
    for (int mt = 0; mt < 2; mt++)
        #pragma unroll
        for (int nt = 0; nt < 8; nt++)
            #pragma unroll
            for (int i = 0; i < 4; i++) {
                int row = wr + mt * 16 + g + (i >> 1) * 8;
                int col = wc + nt * 8 + tg * 2 + (i & 1);
                Tb[row * 132 + col] = __expf(c[mt][nt][i]);
            }
    __syncthreads();

    bf16* Ehi  = g_Ehi  + (size_t)b * NPIX * NPIX;
    bf16* Elo  = g_Elo  + (size_t)b * NPIX * NPIX;
    bf16* EThi = g_EThi + (size_t)b * NPIX * NPIX;
    bf16* ETlo = g_ETlo + (size_t)b * NPIX * NPIX;

    for (int i = t; i < 2048; i += 256) {          // E rows: 8 elems -> uint4
        int r = i >> 4, cg = (i & 15) * 8;
        uint4 hv, lv;
        hv.x = split2(Tb[r * 132 + cg + 0], Tb[r * 132 + cg + 1], lv.x);
        hv.y = split2(Tb[r * 132 + cg + 2], Tb[r * 132 + cg + 3], lv.y);
        hv.z = split2(Tb[r * 132 + cg + 4], Tb[r * 132 + cg + 5], lv.z);
        hv.w = split2(Tb[r * 132 + cg + 6], Tb[r * 132 + cg + 7], lv.w);
        size_t gi = (size_t)(n0 + r) * NPIX + m0 + cg;
        *(uint4*)(Ehi + gi) = hv;
        *(uint4*)(Elo + gi) = lv;
    }
    for (int i = t; i < 2048; i += 256) {          // ET: gather col
        int cl = i >> 4, rq = (i & 15) * 8;
        uint4 hv, lv;
        hv.x = split2(Tb[(rq + 0) * 132 + cl], Tb[(rq + 1) * 132 + cl], lv.x);
        hv.y = split2(Tb[(rq + 2) * 132 + cl], Tb[(rq + 3) * 132 + cl], lv.y);
        hv.z = split2(Tb[(rq + 4) * 132 + cl], Tb[(rq + 5) * 132 + cl], lv.z);
        hv.w = split2(Tb[(rq + 6) * 132 + cl], Tb[(rq + 7) * 132 + cl], lv.w);
        size_t gi = (size_t)(m0 + cl) * NPIX + n0 + rq;
        *(uint4*)(EThi + gi) = hv;
        *(uint4*)(ETlo + gi) = lv;
    }
    if (t < 128) {
        float s = 0.f;
        #pragma unroll 8
        for (int j = 0; j < 128; j++) s += Tb[t * 132 + j];
        atomicAdd(g_rowsum + b * NPIX + n0 + t, s);
    } else {
        int cl = t - 128;
        float s = 0.f;
        #pragma unroll 8
        for (int j = 0; j < 128; j++) s += Tb[j * 132 + cl];
        atomicAdd(g_colsum + b * NPIX + m0 + cl, s);
    }
}

// ============ pv: cp.async double-buffered, pure lds+mma ============
// per stage (uint32 stride 36 = 144B/row, 18432B/array): Ahi Alo Bhi Blo; 2 stages; RS@147456
#define PV_SMEM 147968
__global__ __launch_bounds__(256) void pv_mma(const float* __restrict__ scale_p,
                                              float* __restrict__ outEq,
                                              float* __restrict__ outEs)
{
    extern __shared__ char sm[];
    const int t = threadIdx.x, lane = t & 31, wid = t >> 5;
    const int g = lane >> 2, tg = lane & 3;
    const int r0 = blockIdx.x * 128, b = blockIdx.y, mode = blockIdx.z;
    const int wr = (wid & 3) * 32, wc = (wid >> 2) * 64;
    const bf16* A_hi = (mode ? g_EThi : g_Ehi) + (size_t)b * NPIX * NPIX + (size_t)r0 * NPIX;
    const bf16* A_lo = (mode ? g_ETlo : g_Elo) + (size_t)b * NPIX * NPIX + (size_t)r0 * NPIX;
    const bf16* B_hi = (mode ? g_VQhi : g_VShi) + (size_t)b * CI * NPIX;
    const bf16* B_lo = (mode ? g_VQlo : g_VSlo) + (size_t)b * CI * NPIX;
    const float* sums = (mode ? g_colsum : g_rowsum) + (size_t)b * NPIX + r0;
    const float* T = (mode ? g_TQ : g_ST) + (size_t)b * CI * NPIX;
    float* outp = (mode ? outEq : outEs) + (size_t)b * CI * NPIX;
    uint32_t sb = smem_u32(sm);
    float* RS = (float*)(sm + 147456);
    if (t < 128) RS[t] = scale_p[0] / sums[t];

    // preload chunk 0 -> stage 0
    #pragma unroll
    for (int p = 0; p < 4; p++) {
        int i = t + p * 256;               // 0..1023
        int row = i >> 3, seg = i & 7;     // 8 x 16B = 128B = 64 bf16 per row
        size_t go = (size_t)row * NPIX + seg * 8;
        uint32_t so = row * 144 + seg * 16;
        cp16(sb + so,         A_hi + go);
        cp16(sb + 18432 + so, A_lo + go);
        cp16(sb + 36864 + so, B_hi + go);
        cp16(sb + 55296 + so, B_lo + go);
    }
    CP_COMMIT();

    float c[2][8][4] = {};
    for (int kc = 0; kc < 64; kc++) {
        const int st = kc & 1;
        if (kc + 1 < 64) {
            const int st2 = (kc + 1) & 1;
            #pragma unroll
            for (int p = 0; p < 4; p++) {
                int i = t + p * 256;
                int row = i >> 3, seg = i & 7;
                size_t go = (size_t)row * NPIX + (kc + 1) * 64 + seg * 8;
                uint32_t so = st2 * 73728 + row * 144 + seg * 16;
                cp16(sb + so,         A_hi + go);
                cp16(sb + 18432 + so, A_lo + go);
                cp16(sb + 36864 + so, B_hi + go);
                cp16(sb + 55296 + so, B_lo + go);
            }
            CP_COMMIT();
            CP_WAIT(1);
        } else {
            CP_WAIT(0);
        }
        __syncthreads();
        const uint32_t* Ahi = (const uint32_t*)(sm + st * 73728);
        const uint32_t* Alo = (const uint32_t*)(sm + st * 73728 + 18432);
        const uint32_t* Bhi = (const uint32_t*)(sm + st * 73728 + 36864);
        const uint32_t* Blo = (const uint32_t*)(sm + st * 73728 + 55296);
        #pragma unroll
        for (int kb = 0; kb < 32; kb += 8)
            mma_step<36>(Ahi, Alo, Bhi, Blo, kb, wr, wc, g, tg, c);
        __syncthreads();
    }

    float* Tb = (float*)sm;   // [128][132]
    #pragma unroll
    for (int mt = 0; mt < 2; mt++)
        #pragma unroll
        for (int nt = 0; nt < 8; nt++)
            #pragma unroll
            for (int i = 0; i < 4; i++) {
                int row = wr + mt * 16 + g + (i >> 1) * 8;
                int col = wc + nt * 8 + tg * 2 + (i & 1);
                Tb[row * 132 + col] = c[mt][nt][i] * RS[row];
            }
    __syncthreads();
    for (int i = t; i < 16384; i += 256) {
        int cl = i >> 7, r = i & 127;
        size_t gi = (size_t)cl * NPIX + r0 + r;
        outp[gi] = Tb[r * 132 + cl] + T[gi];
    }
}

// ---------------- fused conv1x1: 12 jobs, bf16 hi/lo or f32 outputs ----------------
__global__ __launch_bounds__(256) void convs_kernel(
    const float* __restrict__ q, const float* __restrict__ s,
    const float* __restrict__ w_v,  const float* __restrict__ b_v,
    const float* __restrict__ w_k1, const float* __restrict__ b_k1,
    const float* __restrict__ w_q1, const float* __restrict__ b_q1,
    const float* __restrict__ w_k2, const float* __restrict__ b_k2,
    const float* __restrict__ w_q2, const float* __restrict__ b_q2,
    const float* __restrict__ w_ts, const float* __restrict__ b_ts,
    const float* __restrict__ gts,  const float* __restrict__ bets,
    const float* __restrict__ mts,  const float* __restrict__ vts,
    const float* __restrict__ w_tq, const float* __restrict__ b_tq,
    const float* __restrict__ gtq,  const float* __restrict__ betq,
    const float* __restrict__ mtq,  const float* __restrict__ vtq)
{
    const int j = blockIdx.z, b = blockIdx.y, n0 = blockIdx.x * 128;
    const float *X, *W, *Bi, *bg = nullptr, *bb = nullptr, *bm = nullptr, *bv = nullptr;
    bf16 *dh = nullptr, *dl = nullptr;
    float* df = nullptr;
    int ocb = 0, co = 0; bool chanmaj = true, hasbn = false;
    switch (j) {
        case 0:  X = q; W = w_v;  Bi = b_v;  dh = g_VQhi; dl = g_VQlo; ocb = 0;  co = 0;  break;
        case 1:  X = q; W = w_v;  Bi = b_v;  dh = g_VQhi; dl = g_VQlo; ocb = 64; co = 64; break;
        case 2:  X = s; W = w_v;  Bi = b_v;  dh = g_VShi; dl = g_VSlo; ocb = 0;  co = 0;  break;
        case 3:  X = s; W = w_v;  Bi = b_v;  dh = g_VShi; dl = g_VSlo; ocb = 64; co = 64; break;
        case 4:  X = q; W = w_k1; Bi = b_k1; dh = g_KThi; dl = g_KTlo; chanmaj = false; co = 0;  break;
        case 5:  X = s; W = w_k2; Bi = b_k2; dh = g_KThi; dl = g_KTlo; chanmaj = false; co = 64; break;
        case 6:  X = q; W = w_q1; Bi = b_q1; dh = g_QThi; dl = g_QTlo; chanmaj = false; co = 0;  break;
        case 7:  X = s; W = w_q2; Bi = b_q2; dh = g_QThi; dl = g_QTlo; chanmaj = false; co = 64; break;
        case 8:  X = s; W = w_ts; Bi = b_ts; df = g_ST; ocb = 0;  co = 0;  hasbn = true; bg = gts; bb = bets; bm = mts; bv = vts; break;
        case 9:  X = s; W = w_ts; Bi = b_ts; df = g_ST; ocb = 64; co = 64; hasbn = true; bg = gts; bb = bets; bm = mts; bv = vts; break;
        case 10: X = q; W = w_tq; Bi = b_tq; df = g_TQ; ocb = 0;  co = 0;  hasbn = true; bg = gtq; bb = betq; bm = mtq; bv = vtq; break;
        default: X = q; W = w_tq; Bi = b_tq; df = g_TQ; ocb = 64; co = 64; hasbn = true; bg = gtq; bb = betq; bm = mtq; bv = vtq; break;
    }
    const float* Xb = X + (size_t)b * NC * NPIX;
    __shared__ float Ws[16][64];
    __shared__ float Xs[16][128];
    float acc[4][8] = {};
    const int t = threadIdx.x, rg = t >> 4, cg = t & 15;

    for (int k0 = 0; k0 < NC; k0 += 16) {
        for (int i = t; i < 1024; i += 256) {
            int oc = i >> 4, kk = i & 15;
            Ws[kk][oc] = W[(ocb + oc) * NC + k0 + kk];
        }
        for (int i = t; i < 2048; i += 256) {
            int kk = i >> 7, px = i & 127;
            Xs[kk][px] = Xb[(size_t)(k0 + kk) * NPIX + n0 + px];
        }
        __syncthreads();
        #pragma unroll
        for (int kk = 0; kk < 16; kk++) {
            float a[4], xv[8];
            #pragma unroll
            for (int i = 0; i < 4; i++) a[i] = Ws[kk][rg * 4 + i];
            #pragma unroll
            for (int jx = 0; jx < 8; jx++) xv[jx] = Xs[kk][cg * 8 + jx];
            #pragma unroll
            for (int i = 0; i < 4; i++)
                #pragma unroll
                for (int jx = 0; jx < 8; jx++) acc[i][jx] += a[i] * xv[jx];
        }
        __syncthreads();
    }
    #pragma unroll
    for (int i = 0; i < 4; i++) {
        int oc = rg * 4 + i, gi = ocb + oc;
        float sc = 1.f, off = Bi[gi];
        if (hasbn) {
            float inv = bg[gi] * rsqrtf(bv[gi] + EPSV);
            sc = inv; off = (Bi[gi] - bm[gi]) * inv + bb[gi];
        }
        #pragma unroll
        for (int jx = 0; jx < 8; jx++) {
            int px = cg * 8 + jx;
            float v = acc[i][jx] * sc + off;
            if (df) {
                df[((size_t)b * CI + co + oc) * NPIX + n0 + px] = v;
            } else {
                size_t idx = chanmaj
                    ? ((size_t)b * CI + co + oc) * NPIX + n0 + px
                    : ((size_t)b * NPIX + n0 + px) * CI + co + oc;
                bf16 h = __float2bfloat16(v);
                dh[idx] = h;
                dl[idx] = __float2bfloat16(v - __bfloat162float(h));
            }
        }
    }
}

// ---------------- 3x3 conv + BN + ReLU ----------------
__global__ __launch_bounds__(256) void conv3x3_kernel(
    const float* __restrict__ Wc,
    const float* __restrict__ bng, const float* __restrict__ bnb,
    const float* __restrict__ bnm, const float* __restrict__ bnv,
    const float* __restrict__ Eq, const float* __restrict__ Es,
    float* __restrict__ outp)
{
    const int b = blockIdx.y, y = blockIdx.x, zh = blockIdx.z;
    __shared__ float Xs[8][3][68];
    __shared__ float Wsm[8][9][64];
    const int t = threadIdx.x, pxg = t & 15, ocg = t >> 4;
    float acc[4][4] = {};

    for (int ic0 = 0; ic0 < 256; ic0 += 8) {
        const float* src = (ic0 < 128)
            ? Eq + ((size_t)b * CI + ic0) * NPIX
            : Es + ((size_t)b * CI + (ic0 - 128)) * NPIX;
        for (int i = t; i < 1584; i += 256) {
            int ic = i / 198, rem = i - ic * 198;
            int dy = rem / 66, xx = rem - dy * 66;
            int xg = xx - 1, yg = y + dy - 1;
            float v = 0.f;
            if (xg >= 0 && xg < 64 && yg >= 0 && yg < 64)
                v = src[(size_t)ic * NPIX + yg * 64 + xg];
            Xs[ic][dy][xx] = v;
        }
        for (int i = t; i < 4608; i += 256) {
            int oc = i / 72, rem = i - oc * 72;
            int icl = rem / 9, tap = rem - icl * 9;
            Wsm[icl][tap][oc] = Wc[(size_t)(zh * 64 + oc) * 2304 + (ic0 + icl) * 9 + tap];
        }
        __syncthreads();
        #pragma unroll
        for (int ic = 0; ic < 8; ic++)
            #pragma unroll
            for (int tap = 0; tap < 9; tap++) {
                const int dy = tap / 3, dx = tap - dy * 3;
                float w[4], xv[4];
                #pragma unroll
                for (int o = 0; o < 4; o++) w[o] = Wsm[ic][tap][ocg * 4 + o];
                #pragma unroll
                for (int p = 0; p < 4; p++) xv[p] = Xs[ic][dy][pxg * 4 + p + dx];
                #pragma unroll
                for (int o = 0; o < 4; o++)
                    #pragma unroll
                    for (int p = 0; p < 4; p++) acc[o][p] += w[o] * xv[p];
            }
        __syncthreads();
    }
    #pragma unroll
    for (int o = 0; o < 4; o++) {
        int oc = zh * 64 + ocg * 4 + o;
        float inv = bng[oc] * rsqrtf(bnv[oc] + EPSV);
        float off = bnb[oc] - bnm[oc] * inv;
        #pragma unroll
        for (int p = 0; p < 4; p++) {
            int px = pxg * 4 + p;
            outp[((size_t)b * CI + oc) * NPIX + y * 64 + px] = fmaxf(acc[o][p] * inv + off, 0.f);
        }
    }
}

// ---------------- launch ----------------
extern "C" void kernel_launch(void* const* d_in, const int* in_sizes, int n_in,
                              void* d_out, int out_size)
{
    (void)in_sizes; (void)n_in; (void)out_size;
    const float* q     = (const float*)d_in[0];
    const float* s     = (const float*)d_in[1];
    const float* scale = (const float*)d_in[2];
    const float* w_v   = (const float*)d_in[3];  const float* b_v  = (const float*)d_in[4];
    const float* w_k1  = (const float*)d_in[5];  const float* b_k1 = (const float*)d_in[6];
    const float* w_q1  = (const float*)d_in[7];  const float* b_q1 = (const float*)d_in[8];
    const float* w_k2  = (const float*)d_in[9];  const float* b_k2 = (const float*)d_in[10];
    const float* w_q2  = (const float*)d_in[11]; const float* b_q2 = (const float*)d_in[12];
    const float* w_ts  = (const float*)d_in[13]; const float* b_ts = (const float*)d_in[14];
    const float* gts   = (const float*)d_in[15]; const float* bets = (const float*)d_in[16];
    const float* mts   = (const float*)d_in[17]; const float* vts  = (const float*)d_in[18];
    const float* w_tq  = (const float*)d_in[19]; const float* b_tq = (const float*)d_in[20];
    const float* gtq   = (const float*)d_in[21]; const float* betq = (const float*)d_in[22];
    const float* mtq   = (const float*)d_in[23]; const float* vtq  = (const float*)d_in[24];
    const float* w_cat = (const float*)d_in[25];
    const float* gcat  = (const float*)d_in[26]; const float* becat= (const float*)d_in[27];
    const float* mcat  = (const float*)d_in[28]; const float* vcat = (const float*)d_in[29];

    float* out  = (float*)d_out;
    float* cpam = out;
    float* Eq   = out + (size_t)NB * CI * NPIX;
    float* Es   = out + 2 * (size_t)NB * CI * NPIX;

    cudaFuncSetAttribute(gemmA_mma, cudaFuncAttributeMaxDynamicSharedMemorySize, GA_SMEM);
    cudaFuncSetAttribute(pv_mma,   cudaFuncAttributeMaxDynamicSharedMemorySize, PV_SMEM);

    zero_sums<<<(NB * NPIX + 255) / 256, 256>>>();
    convs_kernel<<<dim3(32, NB, 12), 256>>>(q, s, w_v, b_v, w_k1, b_k1, w_q1, b_q1,
                                            w_k2, b_k2, w_q2, b_q2, w_ts, b_ts,
                                            gts, bets, mts, vts, w_tq, b_tq,
                                            gtq, betq, mtq, vtq);
    gemmA_mma<<<dim3(32, 32, NB), 256, GA_SMEM>>>();
    pv_mma<<<dim3(32, NB, 2), 256, PV_SMEM>>>(scale, Eq, Es);
    conv3x3_kernel<<<dim3(64, NB, 2), 256>>>(w_cat, gcat, becat, mcat, vcat, Eq, Es, cpam);
}

// round 7
// speedup vs baseline: 1.3169x; 1.0971x over previous
#include <cuda_runtime.h>
#include <cuda_bf16.h>
#include <cstdint>

#define NB   2
#define NC   256
#define NPIX 4096
#define CI   128
#define EPSV 1e-5f

typedef __nv_bfloat16 bf16;

__device__ bf16 g_Ehi [(size_t)NB * NPIX * NPIX];
__device__ bf16 g_Elo [(size_t)NB * NPIX * NPIX];
__device__ bf16 g_EThi[(size_t)NB * NPIX * NPIX];
__device__ bf16 g_ETlo[(size_t)NB * NPIX * NPIX];
__device__ bf16 g_VQhi[(size_t)NB * CI * NPIX];
__device__ bf16 g_VQlo[(size_t)NB * CI * NPIX];
__device__ bf16 g_VShi[(size_t)NB * CI * NPIX];
__device__ bf16 g_VSlo[(size_t)NB * CI * NPIX];
__device__ bf16 g_KThi[(size_t)NB * NPIX * CI];
__device__ bf16 g_KTlo[(size_t)NB * NPIX * CI];
__device__ bf16 g_QThi[(size_t)NB * NPIX * CI];
__device__ bf16 g_QTlo[(size_t)NB * NPIX * CI];
__device__ float g_ST [(size_t)NB * CI * NPIX];
__device__ float g_TQ [(size_t)NB * CI * NPIX];
__device__ float g_rowsum[NB * NPIX];
__device__ float g_colsum[NB * NPIX];
// bf16 planes of E_q / E_s for conv3x3 input
__device__ bf16 g_EQhi[(size_t)NB * CI * NPIX];
__device__ bf16 g_EQlo[(size_t)NB * CI * NPIX];
__device__ bf16 g_EShi[(size_t)NB * CI * NPIX];
__device__ bf16 g_ESlo[(size_t)NB * CI * NPIX];
// repacked conv weights [tap][oc][ic]
__device__ bf16 g_W3hi[9 * 128 * 256];
__device__ bf16 g_W3lo[9 * 128 * 256];

// ---------------- helpers ----------------
__device__ __forceinline__ uint32_t smem_u32(const void* p) {
    uint32_t a;
    asm("{ .reg .u64 t; cvta.to.shared.u64 t, %1; cvt.u32.u64 %0, t; }" : "=r"(a) : "l"(p));
    return a;
}
__device__ __forceinline__ void cp16(uint32_t dst, const void* src) {
    asm volatile("cp.async.cg.shared.global [%0], [%1], 16;" :: "r"(dst), "l"(src));
}
#define CP_COMMIT() asm volatile("cp.async.commit_group;" ::: "memory")
#define CP_WAIT(n)  asm volatile("cp.async.wait_group %0;" :: "n"(n) : "memory")

__device__ __forceinline__ void mma_bf16(float* c, const uint32_t* a, uint32_t b0, uint32_t b1) {
    asm("mma.sync.aligned.m16n8k16.row.col.f32.bf16.bf16.f32 "
        "{%0,%1,%2,%3},{%4,%5,%6,%7},{%8,%9},{%0,%1,%2,%3};"
        : "+f"(c[0]), "+f"(c[1]), "+f"(c[2]), "+f"(c[3])
        : "r"(a[0]), "r"(a[1]), "r"(a[2]), "r"(a[3]), "r"(b0), "r"(b1));
}
__device__ __forceinline__ uint32_t split2(float x, float y, uint32_t& lo) {
    bf16 hx = __float2bfloat16(x), hy = __float2bfloat16(y);
    uint32_t hi = (uint32_t)__bfloat16_as_ushort(hx) | ((uint32_t)__bfloat16_as_ushort(hy) << 16);
    bf16 lx = __float2bfloat16(x - __bfloat162float(hx));
    bf16 ly = __float2bfloat16(y - __bfloat162float(hy));
    lo = (uint32_t)__bfloat16_as_ushort(lx) | ((uint32_t)__bfloat16_as_ushort(ly) << 16);
    return hi;
}

template<int ST>
__device__ __forceinline__ void mma_step(const uint32_t* Ahi, const uint32_t* Alo,
                                         const uint32_t* Bhi, const uint32_t* Blo,
                                         int kb, int wr, int wc, int g, int tg, float c[2][8][4])
{
    uint32_t ah[2][4], al[2][4];
    #pragma unroll
    for (int mt = 0; mt < 2; mt++) {
        int base = (wr + mt * 16 + g) * ST + kb + tg;
        ah[mt][0] = Ahi[base];          ah[mt][1] = Ahi[base + 8 * ST];
        ah[mt][2] = Ahi[base + 4];      ah[mt][3] = Ahi[base + 8 * ST + 4];
        al[mt][0] = Alo[base];          al[mt][1] = Alo[base + 8 * ST];
        al[mt][2] = Alo[base + 4];      al[mt][3] = Alo[base + 8 * ST + 4];
    }
    #pragma unroll
    for (int nt = 0; nt < 8; nt++) {
        int bb = (wc + nt * 8 + g) * ST + kb + tg;
        uint32_t bh0 = Bhi[bb], bh1 = Bhi[bb + 4];
        uint32_t bl0 = Blo[bb], bl1 = Blo[bb + 4];
        #pragma unroll
        for (int mt = 0; mt < 2; mt++) {
            mma_bf16(c[mt][nt], ah[mt], bh0, bh1);
            mma_bf16(c[mt][nt], al[mt], bh0, bh1);
            mma_bf16(c[mt][nt], ah[mt], bl0, bl1);
        }
    }
}

__global__ void zero_sums() {
    int i = blockIdx.x * 256 + threadIdx.x;
    if (i < NB * NPIX) { g_rowsum[i] = 0.f; g_colsum[i] = 0.f; }
}

// repack w_cat [oc][256][3][3] -> [tap][oc][ic] bf16 hi/lo
__global__ void w3prep(const float* __restrict__ Wc) {
    int i = blockIdx.x * 256 + threadIdx.x;
    if (i >= 9 * 128 * 256) return;
    int tap = i >> 15, oc = (i >> 8) & 127, ic = i & 255;
    float v = Wc[(size_t)oc * 2304 + ic * 9 + tap];
    bf16 h = __float2bfloat16(v);
    g_W3hi[i] = h;
    g_W3lo[i] = __float2bfloat16(v - __bfloat162float(h));
}

// ============ gemmA ============
#define GA_SMEM 139264
__global__ __launch_bounds__(256) void gemmA_mma()
{
    extern __shared__ char sm[];
    const int t = threadIdx.x, lane = t & 31, wid = t >> 5;
    const int g = lane >> 2, tg = lane & 3;
    const int b = blockIdx.z, n0 = blockIdx.x * 128, m0 = blockIdx.y * 128;
    const int wr = (wid & 3) * 32, wc = (wid >> 2) * 64;
    const bf16* A_hi = g_KThi + (size_t)b * NPIX * CI + (size_t)n0 * CI;
    const bf16* A_lo = g_KTlo + (size_t)b * NPIX * CI + (size_t)n0 * CI;
    const bf16* B_hi = g_QThi + (size_t)b * NPIX * CI + (size_t)m0 * CI;
    const bf16* B_lo = g_QTlo + (size_t)b * NPIX * CI + (size_t)m0 * CI;
    uint32_t sb = smem_u32(sm);

    #pragma unroll
    for (int p = 0; p < 8; p++) {
        int i = t + p * 256;
        int row = i >> 4, seg = i & 15;
        size_t go = (size_t)row * CI + seg * 8;
        uint32_t so = row * 272 + seg * 16;
        cp16(sb + so,          A_hi + go);
        cp16(sb + 34816 + so,  A_lo + go);
        cp16(sb + 69632 + so,  B_hi + go);
        cp16(sb + 104448 + so, B_lo + go);
    }
    CP_COMMIT();
    CP_WAIT(0);
    __syncthreads();

    const uint32_t* Ahi = (const uint32_t*)sm;
    const uint32_t* Alo = (const uint32_t*)(sm + 34816);
    const uint32_t* Bhi = (const uint32_t*)(sm + 69632);
    const uint32_t* Blo = (const uint32_t*)(sm + 104448);
    float c[2][8][4] = {};
    #pragma unroll
    for (int kb = 0; kb < 64; kb += 8)
        mma_step<68>(Ahi, Alo, Bhi, Blo, kb, wr, wc, g, tg, c);
    __syncthreads();

    float* Tb = (float*)sm;
    #pragma unroll
    for (int mt = 0; mt < 2; mt++)
        #pragma unroll
        for (int nt = 0; nt < 8; nt++)
            #pragma unroll
            for (int i = 0; i < 4; i++) {
                int row = wr + mt * 16 + g + (i >> 1) * 8;
                int col = wc + nt * 8 + tg * 2 + (i & 1);
                Tb[row * 132 + col] = __expf(c[mt][nt][i]);
            }
    __syncthreads();

    bf16* Ehi  = g_Ehi  + (size_t)b * NPIX * NPIX;
    bf16* Elo  = g_Elo  + (size_t)b * NPIX * NPIX;
    bf16* EThi = g_EThi + (size_t)b * NPIX * NPIX;
    bf16* ETlo = g_ETlo + (size_t)b * NPIX * NPIX;

    for (int i = t; i < 2048; i += 256) {
        int r = i >> 4, cg = (i & 15) * 8;
        uint4 hv, lv;
        hv.x = split2(Tb[r * 132 + cg + 0], Tb[r * 132 + cg + 1], lv.x);
        hv.y = split2(Tb[r * 132 + cg + 2], Tb[r * 132 + cg + 3], lv.y);
        hv.z = split2(Tb[r * 132 + cg + 4], Tb[r * 132 + cg + 5], lv.z);
        hv.w = split2(Tb[r * 132 + cg + 6], Tb[r * 132 + cg + 7], lv.w);
        size_t gi = (size_t)(n0 + r) * NPIX + m0 + cg;
        *(uint4*)(Ehi + gi) = hv;
        *(uint4*)(Elo + gi) = lv;
    }
    for (int i = t; i < 2048; i += 256) {
        int cl = i >> 4, rq = (i & 15) * 8;
        uint4 hv, lv;
        hv.x = split2(Tb[(rq + 0) * 132 + cl], Tb[(rq + 1) * 132 + cl], lv.x);
        hv.y = split2(Tb[(rq + 2) * 132 + cl], Tb[(rq + 3) * 132 + cl], lv.y);
        hv.z = split2(Tb[(rq + 4) * 132 + cl], Tb[(rq + 5) * 132 + cl], lv.z);
        hv.w = split2(Tb[(rq + 6) * 132 + cl], Tb[(rq + 7) * 132 + cl], lv.w);
        size_t gi = (size_t)(m0 + cl) * NPIX + n0 + rq;
        *(uint4*)(EThi + gi) = hv;
        *(uint4*)(ETlo + gi) = lv;
    }
    if (t < 128) {
        float s = 0.f;
        #pragma unroll 8
        for (int j = 0; j < 128; j++) s += Tb[t * 132 + j];
        atomicAdd(g_rowsum + b * NPIX + n0 + t, s);
    } else {
        int cl = t - 128;
        float s = 0.f;
        #pragma unroll 8
        for (int j = 0; j < 128; j++) s += Tb[j * 132 + cl];
        atomicAdd(g_colsum + b * NPIX + m0 + cl, s);
    }
}

// ============ pv ============
#define PV_SMEM 147968
__global__ __launch_bounds__(256) void pv_mma(const float* __restrict__ scale_p,
                                              float* __restrict__ outEq,
                                              float* __restrict__ outEs)
{
    extern __shared__ char sm[];
    const int t = threadIdx.x, lane = t & 31, wid = t >> 5;
    const int g = lane >> 2, tg = lane & 3;
    const int r0 = blockIdx.x * 128, b = blockIdx.y, mode = blockIdx.z;
    const int wr = (wid & 3) * 32, wc = (wid >> 2) * 64;
    const bf16* A_hi = (mode ? g_EThi : g_Ehi) + (size_t)b * NPIX * NPIX + (size_t)r0 * NPIX;
    const bf16* A_lo = (mode ? g_ETlo : g_Elo) + (size_t)b * NPIX * NPIX + (size_t)r0 * NPIX;
    const bf16* B_hi = (mode ? g_VQhi : g_VShi) + (size_t)b * CI * NPIX;
    const bf16* B_lo = (mode ? g_VQlo : g_VSlo) + (size_t)b * CI * NPIX;
    const float* sums = (mode ? g_colsum : g_rowsum) + (size_t)b * NPIX + r0;
    const float* T = (mode ? g_TQ : g_ST) + (size_t)b * CI * NPIX;
    float* outp = (mode ? outEq : outEs) + (size_t)b * CI * NPIX;
    bf16* Fh = (mode ? g_EQhi : g_EShi) + (size_t)b * CI * NPIX;
    bf16* Fl = (mode ? g_EQlo : g_ESlo) + (size_t)b * CI * NPIX;
    uint32_t sb = smem_u32(sm);
    float* RS = (float*)(sm + 147456);
    if (t < 128) RS[t] = scale_p[0] / sums[t];

    #pragma unroll
    for (int p = 0; p < 4; p++) {
        int i = t + p * 256;
        int row = i >> 3, seg = i & 7;
        size_t go = (size_t)row * NPIX + seg * 8;
        uint32_t so = row * 144 + seg * 16;
        cp16(sb + so,         A_hi + go);
        cp16(sb + 18432 + so, A_lo + go);
        cp16(sb + 36864 + so, B_hi + go);
        cp16(sb + 55296 + so, B_lo + go);
    }
    CP_COMMIT();

    float c[2][8][4] = {};
    for (int kc = 0; kc < 64; kc++) {
        const int st = kc & 1;
        if (kc + 1 < 64) {
            const int st2 = (kc + 1) & 1;
            #pragma unroll
            for (int p = 0; p < 4; p++) {
                int i = t + p * 256;
                int row = i >> 3, seg = i & 7;
                size_t go = (size_t)row * NPIX + (kc + 1) * 64 + seg * 8;
                uint32_t so = st2 * 73728 + row * 144 + seg * 16;
                cp16(sb + so,         A_hi + go);
                cp16(sb + 18432 + so, A_lo + go);
                cp16(sb + 36864 + so, B_hi + go);
                cp16(sb + 55296 + so, B_lo + go);
            }
            CP_COMMIT();
            CP_WAIT(1);
        } else {
            CP_WAIT(0);
        }
        __syncthreads();
        const uint32_t* Ahi = (const uint32_t*)(sm + st * 73728);
        const uint32_t* Alo = (const uint32_t*)(sm + st * 73728 + 18432);
        const uint32_t* Bhi = (const uint32_t*)(sm + st * 73728 + 36864);
        const uint32_t* Blo = (const uint32_t*)(sm + st * 73728 + 55296);
        #pragma unroll
        for (int kb = 0; kb < 32; kb += 8)
            mma_step<36>(Ahi, Alo, Bhi, Blo, kb, wr, wc, g, tg, c);
        __syncthreads();
    }

    float* Tb = (float*)sm;
    #pragma unroll
    for (int mt = 0; mt < 2; mt++)
        #pragma unroll
        for (int nt = 0; nt < 8; nt++)
            #pragma unroll
            for (int i = 0; i < 4; i++) {
                int row = wr + mt * 16 + g + (i >> 1) * 8;
                int col = wc + nt * 8 + tg * 2 + (i & 1);
                Tb[row * 132 + col] = c[mt][nt][i] * RS[row];
            }
    __syncthreads();
    for (int i = t; i < 16384; i += 256) {
        int cl = i >> 7, r = i & 127;
        size_t gi = (size_t)cl * NPIX + r0 + r;
        float v = Tb[r * 132 + cl] + T[gi];
        outp[gi] = v;
        bf16 h = __float2bfloat16(v);
        Fh[gi] = h;
        Fl[gi] = __float2bfloat16(v - __bfloat162float(h));
    }
}

// ---------------- fused conv1x1: 12 jobs ----------------
__global__ __launch_bounds__(256) void convs_kernel(
    const float* __restrict__ q, const float* __restrict__ s,
    const float* __restrict__ w_v,  const float* __restrict__ b_v,
    const float* __restrict__ w_k1, const float* __restrict__ b_k1,
    const float* __restrict__ w_q1, const float* __restrict__ b_q1,
    const float* __restrict__ w_k2, const float* __restrict__ b_k2,
    const float* __restrict__ w_q2, const float* __restrict__ b_q2,
    const float* __restrict__ w_ts, const float* __restrict__ b_ts,
    const float* __restrict__ gts,  const float* __restrict__ bets,
    const float* __restrict__ mts,  const float* __restrict__ vts,
    const float* __restrict__ w_tq, const float* __restrict__ b_tq,
    const float* __restrict__ gtq,  const float* __restrict__ betq,
    const float* __restrict__ mtq,  const float* __restrict__ vtq)
{
    const int j = blockIdx.z, b = blockIdx.y, n0 = blockIdx.x * 128;
    const float *X, *W, *Bi, *bg = nullptr, *bb = nullptr, *bm = nullptr, *bv = nullptr;
    bf16 *dh = nullptr, *dl = nullptr;
    float* df = nullptr;
    int ocb = 0, co = 0; bool chanmaj = true, hasbn = false;
    switch (j) {
        case 0:  X = q; W = w_v;  Bi = b_v;  dh = g_VQhi; dl = g_VQlo; ocb = 0;  co = 0;  break;
        case 1:  X = q; W = w_v;  Bi = b_v;  dh = g_VQhi; dl = g_VQlo; ocb = 64; co = 64; break;
        case 2:  X = s; W = w_v;  Bi = b_v;  dh = g_VShi; dl = g_VSlo; ocb = 0;  co = 0;  break;
        case 3:  X = s; W = w_v;  Bi = b_v;  dh = g_VShi; dl = g_VSlo; ocb = 64; co = 64; break;
        case 4:  X = q; W = w_k1; Bi = b_k1; dh = g_KThi; dl = g_KTlo; chanmaj = false; co = 0;  break;
        case 5:  X = s; W = w_k2; Bi = b_k2; dh = g_KThi; dl = g_KTlo; chanmaj = false; co = 64; break;
        case 6:  X = q; W = w_q1; Bi = b_q1; dh = g_QThi; dl = g_QTlo; chanmaj = false; co = 0;  break;
        case 7:  X = s; W = w_q2; Bi = b_q2; dh = g_QThi; dl = g_QTlo; chanmaj = false; co = 64; break;
        case 8:  X = s; W = w_ts; Bi = b_ts; df = g_ST; ocb = 0;  co = 0;  hasbn = true; bg = gts; bb = bets; bm = mts; bv = vts; break;
        case 9:  X = s; W = w_ts; Bi = b_ts; df = g_ST; ocb = 64; co = 64; hasbn = true; bg = gts; bb = bets; bm = mts; bv = vts; break;
        case 10: X = q; W = w_tq; Bi = b_tq; df = g_TQ; ocb = 0;  co = 0;  hasbn = true; bg = gtq; bb = betq; bm = mtq; bv = vtq; break;
        default: X = q; W = w_tq; Bi = b_tq; df = g_TQ; ocb = 64; co = 64; hasbn = true; bg = gtq; bb = betq; bm = mtq; bv = vtq; break;
    }
    const float* Xb = X + (size_t)b * NC * NPIX;
    __shared__ float Ws[16][64];
    __shared__ float Xs[16][128];
    float acc[4][8] = {};
    const int t = threadIdx.x, rg = t >> 4, cg = t & 15;

    for (int k0 = 0; k0 < NC; k0 += 16) {
        for (int i = t; i < 1024; i += 256) {
            int oc = i >> 4, kk = i & 15;
            Ws[kk][oc] = W[(ocb + oc) * NC + k0 + kk];
        }
        for (int i = t; i < 2048; i += 256) {
            int kk = i >> 7, px = i & 127;
            Xs[kk][px] = Xb[(size_t)(k0 + kk) * NPIX + n0 + px];
        }
        __syncthreads();
        #pragma unroll
        for (int kk = 0; kk < 16; kk++) {
            float a[4], xv[8];
            #pragma unroll
            for (int i = 0; i < 4; i++) a[i] = Ws[kk][rg * 4 + i];
            #pragma unroll
            for (int jx = 0; jx < 8; jx++) xv[jx] = Xs[kk][cg * 8 + jx];
            #pragma unroll
            for (int i = 0; i < 4; i++)
                #pragma unroll
                for (int jx = 0; jx < 8; jx++) acc[i][jx] += a[i] * xv[jx];
        }
        __syncthreads();
    }
    #pragma unroll
    for (int i = 0; i < 4; i++) {
        int oc = rg * 4 + i, gi = ocb + oc;
        float sc = 1.f, off = Bi[gi];
        if (hasbn) {
            float inv = bg[gi] * rsqrtf(bv[gi] + EPSV);
            sc = inv; off = (Bi[gi] - bm[gi]) * inv + bb[gi];
        }
        #pragma unroll
        for (int jx = 0; jx < 8; jx++) {
            int px = cg * 8 + jx;
            float v = acc[i][jx] * sc + off;
            if (df) {
                df[((size_t)b * CI + co + oc) * NPIX + n0 + px] = v;
            } else {
                size_t idx = chanmaj
                    ? ((size_t)b * CI + co + oc) * NPIX + n0 + px
                    : ((size_t)b * NPIX + n0 + px) * CI + co + oc;
                bf16 h = __float2bfloat16(v);
                dh[idx] = h;
                dl[idx] = __float2bfloat16(v - __bfloat162float(h));
            }
        }
    }
}

// ---------------- conv3x3 via bf16x3 mma: 9 shifted GEMMs ----------------
// smem: XHI@0 XLO@15840 WHI@31680 WLO@41920 (strides 20 u32); Tb[128][68] aliases
#define C3_SMEM 52160
__global__ __launch_bounds__(256) void conv3x3_mma(
    const float* __restrict__ bng, const float* __restrict__ bnb,
    const float* __restrict__ bnm, const float* __restrict__ bnv,
    float* __restrict__ outp_all)
{
    extern __shared__ char sm[];
    const int t = threadIdx.x, lane = t & 31, wid = t >> 5;
    const int g = lane >> 2, tg = lane & 3;
    const int y = blockIdx.x, b = blockIdx.y;
    const int wr = (wid & 3) * 32, wc = (wid >> 2) * 32;
    const bf16* EQh = g_EQhi + (size_t)b * CI * NPIX;
    const bf16* EQl = g_EQlo + (size_t)b * CI * NPIX;
    const bf16* ESh = g_EShi + (size_t)b * CI * NPIX;
    const bf16* ESl = g_ESlo + (size_t)b * CI * NPIX;
    float* outp = outp_all + (size_t)b * CI * NPIX;
    bf16* XH = (bf16*)(sm);
    bf16* XL = (bf16*)(sm + 15840);
    bf16* WHp = (bf16*)(sm + 31680);
    bf16* WLp = (bf16*)(sm + 41920);

    float c[2][4][4] = {};
    for (int icc = 0; icc < 8; icc++) {
        // X slab: 32 ic x 3 rows x 66 px, transposed [n'][ic]
        for (int i = t; i < 32 * 198; i += 256) {
            int icl = i / 198, np = i - icl * 198;
            int r = np / 66, px = np - r * 66;
            int icg = icc * 32 + icl;
            int rg = y + r - 1, x = px - 1;
            bf16 vh = __ushort_as_bfloat16(0), vl = __ushort_as_bfloat16(0);
            if (rg >= 0 && rg < 64 && x >= 0 && x < 64) {
                size_t gi = (size_t)(icg & 127) * NPIX + rg * 64 + x;
                if (icg < 128) { vh = EQh[gi]; vl = EQl[gi]; }
                else           { vh = ESh[gi]; vl = ESl[gi]; }
            }
            XH[np * 40 + icl] = vh;
            XL[np * 40 + icl] = vl;
        }
        __syncthreads();
        for (int tap = 0; tap < 9; tap++) {
            const int dy = tap / 3, dx = tap - dy * 3;
            for (int i = t; i < 4096; i += 256) {
                int oc = i >> 5, icl = i & 31;
                size_t wi = (size_t)tap * 32768 + oc * 256 + icc * 32 + icl;
                WHp[oc * 40 + icl] = g_W3hi[wi];
                WLp[oc * 40 + icl] = g_W3lo[wi];
            }
            __syncthreads();
            const uint32_t* Whi = (const uint32_t*)WHp;
            const uint32_t* Wlo = (const uint32_t*)WLp;
            const uint32_t* Xhi = (const uint32_t*)XH;
            const uint32_t* Xlo = (const uint32_t*)XL;
            #pragma unroll
            for (int kb = 0; kb < 16; kb += 8) {
                uint32_t ah[2][4], al[2][4];
                #pragma unroll
                for (int mt = 0; mt < 2; mt++) {
                    int base = (wr + mt * 16 + g) * 20 + kb + tg;
                    ah[mt][0] = Whi[base];       ah[mt][1] = Whi[base + 160];
                    ah[mt][2] = Whi[base + 4];   ah[mt][3] = Whi[base + 164];
                    al[mt][0] = Wlo[base];       al[mt][1] = Wlo[base + 160];
                    al[mt][2] = Wlo[base + 4];   al[mt][3] = Wlo[base + 164];
                }
                #pragma unroll
                for (int nt = 0; nt < 4; nt++) {
                    int px = wc + nt * 8 + g;
                    int bb = (dy * 66 + px + dx) * 20 + kb + tg;
                    uint32_t bh0 = Xhi[bb], bh1 = Xhi[bb + 4];
                    uint32_t bl0 = Xlo[bb], bl1 = Xlo[bb + 4];
                    #pragma unroll
                    for (int mt = 0; mt < 2; mt++) {
                        mma_bf16(c[mt][nt], ah[mt], bh0, bh1);
                        mma_bf16(c[mt][nt], al[mt], bh0, bh1);
                        mma_bf16(c[mt][nt], ah[mt], bl0, bl1);
                    }
                }
            }
            __syncthreads();
        }
    }

    float* Tb = (float*)sm;   // [128][68]
    #pragma unroll
    for (int mt = 0; mt < 2; mt++)
        #pragma unroll
        for (int nt = 0; nt < 4; nt++)
            #pragma unroll
            for (int i = 0; i < 4; i++) {
                int row = wr + mt * 16 + g + (i >> 1) * 8;
                int col = wc + nt * 8 + tg * 2 + (i & 1);
                Tb[row * 68 + col] = c[mt][nt][i];
            }
    __syncthreads();
    for (int i = t; i < 8192; i += 256) {
        int oc = i >> 6, n = i & 63;
        float inv = bng[oc] * rsqrtf(bnv[oc] + EPSV);
        float off = bnb[oc] - bnm[oc] * inv;
        outp[(size_t)oc * NPIX + y * 64 + n] = fmaxf(Tb[oc * 68 + n] * inv + off, 0.f);
    }
}

// ---------------- launch ----------------
extern "C" void kernel_launch(void* const* d_in, const int* in_sizes, int n_in,
                              void* d_out, int out_size)
{
    (void)in_sizes; (void)n_in; (void)out_size;
    const float* q     = (const float*)d_in[0];
    const float* s     = (const float*)d_in[1];
    const float* scale = (const float*)d_in[2];
    const float* w_v   = (const float*)d_in[3];  const float* b_v  = (const float*)d_in[4];
    const float* w_k1  = (const float*)d_in[5];  const float* b_k1 = (const float*)d_in[6];
    const float* w_q1  = (const float*)d_in[7];  const float* b_q1 = (const float*)d_in[8];
    const float* w_k2  = (const float*)d_in[9];  const float* b_k2 = (const float*)d_in[10];
    const float* w_q2  = (const float*)d_in[11]; const float* b_q2 = (const float*)d_in[12];
    const float* w_ts  = (const float*)d_in[13]; const float* b_ts = (const float*)d_in[14];
    const float* gts   = (const float*)d_in[15]; const float* bets = (const float*)d_in[16];
    const float* mts   = (const float*)d_in[17]; const float* vts  = (const float*)d_in[18];
    const float* w_tq  = (const float*)d_in[19]; const float* b_tq = (const float*)d_in[20];
    const float* gtq   = (const float*)d_in[21]; const float* betq = (const float*)d_in[22];
    const float* mtq   = (const float*)d_in[23]; const float* vtq  = (const float*)d_in[24];
    const float* w_cat = (const float*)d_in[25];
    const float* gcat  = (const float*)d_in[26]; const float* becat= (const float*)d_in[27];
    const float* mcat  = (const float*)d_in[28]; const float* vcat = (const float*)d_in[29];

    float* out  = (float*)d_out;
    float* cpam = out;
    float* Eq   = out + (size_t)NB * CI * NPIX;
    float* Es   = out + 2 * (size_t)NB * CI * NPIX;

    cudaFuncSetAttribute(gemmA_mma,   cudaFuncAttributeMaxDynamicSharedMemorySize, GA_SMEM);
    cudaFuncSetAttribute(pv_mma,      cudaFuncAttributeMaxDynamicSharedMemorySize, PV_SMEM);
    cudaFuncSetAttribute(conv3x3_mma, cudaFuncAttributeMaxDynamicSharedMemorySize, C3_SMEM);

    zero_sums<<<(NB * NPIX + 255) / 256, 256>>>();
    w3prep<<<(9 * 128 * 256 + 255) / 256, 256>>>(w_cat);
    convs_kernel<<<dim3(32, NB, 12), 256>>>(q, s, w_v, b_v, w_k1, b_k1, w_q1, b_q1,
                                            w_k2, b_k2, w_q2, b_q2, w_ts, b_ts,
                                            gts, bets, mts, vts, w_tq, b_tq,
                                            gtq, betq, mtq, vtq);
    gemmA_mma<<<dim3(32, 32, NB), 256, GA_SMEM>>>();
    pv_mma<<<dim3(32, NB, 2), 256, PV_SMEM>>>(scale, Eq, Es);
    conv3x3_mma<<<dim3(64, NB), 256, C3_SMEM>>>(gcat, becat, mcat, vcat, cpam);
}